// round 9
// baseline (speedup 1.0000x reference)
#include <cuda_runtime.h>
#include <cuda_bf16.h>
#include <math.h>

// Problem constants
#define BATCH 8
#define SEQ   1024
#define CDIM  768
#define NH    12
#define HD    64
#define MTOT  (BATCH*SEQ)          // 8192
#define QK_SCALE 0.125f            // 64^-0.5

// ---------------------------------------------------------------------------
// Scratch (device globals — no allocations allowed)
// ---------------------------------------------------------------------------
__device__ float g_q[BATCH*NH*SEQ*HD];     // [b,h,n,d], pre-scaled by QK_SCALE
__device__ float g_k[BATCH*NH*SEQ*HD];     // [b,h,n,d]
__device__ float g_v[BATCH*NH*SEQ*HD];     // [b,h,n,d]
__device__ float g_ctx[BATCH*SEQ*CDIM];    // [b,n,c] attention output

// ---------------------------------------------------------------------------
// f32x2 packed-FMA helpers (FFMA2 path — ptxas won't auto-fuse from C++)
// ---------------------------------------------------------------------------
typedef unsigned long long u64;
__device__ __forceinline__ u64 pack2(float lo, float hi) {
    u64 r; asm("mov.b64 %0, {%1, %2};" : "=l"(r) : "f"(lo), "f"(hi)); return r;
}
__device__ __forceinline__ float2 unpack2(u64 v) {
    float2 o; asm("mov.b64 {%0, %1}, %2;" : "=f"(o.x), "=f"(o.y) : "l"(v)); return o;
}
__device__ __forceinline__ void ffma2(u64 &d, u64 a, u64 b) {
    asm("fma.rn.f32x2 %0, %1, %2, %0;" : "+l"(d) : "l"(a), "l"(b));
}

// ---------------------------------------------------------------------------
// QKV scatter epilogue: f in [0,2304) -> {q,k,v}[b,h,n,d]
// ---------------------------------------------------------------------------
__device__ __forceinline__ void store_qkv(int m, int f, float val) {
    int b = m >> 10, n = m & 1023;
    int which = f / CDIM;
    int rr = f - which * CDIM;
    int h = rr >> 6, d = rr & 63;
    float* dst = (which == 0) ? g_q : (which == 1) ? g_k : g_v;
    if (which == 0) val *= QK_SCALE;            // fold scale into Q
    dst[((size_t)(b * NH + h) * SEQ + n) * HD + d] = val;
}

// ---------------------------------------------------------------------------
// SGEMM: C[m,f] = sum_k A[m,k] * W[f,k]
//   MODE 0: A = x, scatter into g_q/g_k/g_v        (M=8192, N=2304, K=768)
//   MODE 1: A = g_ctx, out = C + bias              (M=8192, N=768,  K=768)
// 128x128x16 tile, 256 threads, 8x8 microtile, f32x2 accumulators.
// All dims are exact multiples of the tile — no bounds checks.
// ---------------------------------------------------------------------------
#define GAP 132   // padded smem pitch (floats)

template<int MODE>
__global__ __launch_bounds__(256, 2)
void sgemm_kernel(const float* __restrict__ A,
                  const float* __restrict__ W,
                  const float* __restrict__ bias,
                  float* __restrict__ out)
{
    const int K = CDIM;
    __shared__ __align__(16) float As[16 * GAP];
    __shared__ __align__(16) float Bs[16 * GAP];

    const int tid = threadIdx.x;
    const int m0 = blockIdx.y * 128;
    const int f0 = blockIdx.x * 128;
    const int tr = (tid >> 4) << 3;    // row offset within tile (0..120)
    const int tc = (tid & 15) << 3;    // col offset within tile (0..120)

    const float* Ap = (MODE == 0) ? A : g_ctx;

    u64 acc[8][4];
    #pragma unroll
    for (int i = 0; i < 8; i++)
        #pragma unroll
        for (int j = 0; j < 4; j++) acc[i][j] = 0ull;

    for (int k0 = 0; k0 < K; k0 += 16) {
        // load 128x16 A-tile and 128x16 W-tile, transposed into smem
        #pragma unroll
        for (int t = 0; t < 2; t++) {
            int l = tid + (t << 8);          // 0..511
            int row = l >> 2;                // 0..127
            int kq = (l & 3) << 2;           // 0,4,8,12
            float4 av = *(const float4*)(Ap + (size_t)(m0 + row) * K + k0 + kq);
            As[(kq + 0) * GAP + row] = av.x;
            As[(kq + 1) * GAP + row] = av.y;
            As[(kq + 2) * GAP + row] = av.z;
            As[(kq + 3) * GAP + row] = av.w;
            float4 bv = *(const float4*)(W + (size_t)(f0 + row) * K + k0 + kq);
            Bs[(kq + 0) * GAP + row] = bv.x;
            Bs[(kq + 1) * GAP + row] = bv.y;
            Bs[(kq + 2) * GAP + row] = bv.z;
            Bs[(kq + 3) * GAP + row] = bv.w;
        }
        __syncthreads();

        #pragma unroll
        for (int k = 0; k < 16; k++) {
            float4 a0 = *(const float4*)&As[k * GAP + tr];
            float4 a1 = *(const float4*)&As[k * GAP + tr + 4];
            float4 b0 = *(const float4*)&Bs[k * GAP + tc];
            float4 b1 = *(const float4*)&Bs[k * GAP + tc + 4];
            u64 rb[4] = { pack2(b0.x, b0.y), pack2(b0.z, b0.w),
                          pack2(b1.x, b1.y), pack2(b1.z, b1.w) };
            float ra[8] = { a0.x, a0.y, a0.z, a0.w, a1.x, a1.y, a1.z, a1.w };
            #pragma unroll
            for (int i = 0; i < 8; i++) {
                u64 aa = pack2(ra[i], ra[i]);
                #pragma unroll
                for (int j = 0; j < 4; j++) ffma2(acc[i][j], aa, rb[j]);
            }
        }
        __syncthreads();
    }

    // epilogue
    #pragma unroll
    for (int i = 0; i < 8; i++) {
        int m = m0 + tr + i;
        #pragma unroll
        for (int j = 0; j < 4; j++) {
            float2 v = unpack2(acc[i][j]);
            int f = f0 + tc + 2 * j;
            if (MODE == 0) {
                store_qkv(m, f, v.x);
                store_qkv(m, f + 1, v.y);
            } else {
                out[(size_t)m * CDIM + f]     = v.x + bias[f];
                out[(size_t)m * CDIM + f + 1] = v.y + bias[f + 1];
            }
        }
    }
}

// ---------------------------------------------------------------------------
// Flash-style attention. Grid: (SEQ/64, B*H), 256 threads.
// Each CTA: 64 query rows of one (b,h). K/V tiles of 64 rows.
// Thread (ty,tx) = (tid>>4, tid&15) owns rows {ty+16*ii}, cols/dims {tx+16*jj}.
// Dynamic smem: Qs[64*64] + Kt[64*65] (K transposed, padded) + Vs[64*64] + Ps[64*64]
// ---------------------------------------------------------------------------
#define ATTN_SMEM_FLOATS (64*64 + 64*65 + 64*64 + 64*64)   // 16448
#define ATTN_SMEM_BYTES  (ATTN_SMEM_FLOATS * 4)            // 65792

__global__ __launch_bounds__(256, 2)
void attn_kernel()
{
    extern __shared__ __align__(16) float sm[];
    float* Qs = sm;                  // [64][64]
    float* Kt = Qs + 64 * 64;        // [64][65]  (Kt[d][j])
    float* Vs = Kt + 64 * 65;        // [64][64]
    float* Ps = Vs + 64 * 64;        // [64][64]

    const int tid = threadIdx.x;
    const int tx = tid & 15, ty = tid >> 4;
    const int bh = blockIdx.y, qt = blockIdx.x;

    const float* Qg = g_q + (size_t)bh * SEQ * HD;
    const float* Kg = g_k + (size_t)bh * SEQ * HD;
    const float* Vg = g_v + (size_t)bh * SEQ * HD;

    // load 64x64 Q tile (Q already scaled)
    #pragma unroll
    for (int t = 0; t < 4; t++) {
        int l = tid + (t << 8);
        int r = l >> 4, dq = (l & 15) << 2;
        *(float4*)&Qs[r * 64 + dq] =
            *(const float4*)(Qg + (size_t)(qt * 64 + r) * HD + dq);
    }

    float m_i[4], l_i[4], o[4][4];
    #pragma unroll
    for (int ii = 0; ii < 4; ii++) {
        m_i[ii] = -INFINITY; l_i[ii] = 0.f;
        #pragma unroll
        for (int jj = 0; jj < 4; jj++) o[ii][jj] = 0.f;
    }

    for (int kt = 0; kt < SEQ / 64; kt++) {
        __syncthreads();   // covers Q-load on kt=0, protects Kt/Vs/Ps reuse after

        // load K tile transposed + V tile
        #pragma unroll
        for (int t = 0; t < 4; t++) {
            int l = tid + (t << 8);
            int j = l >> 4, dq = (l & 15) << 2;
            float4 kv = *(const float4*)(Kg + (size_t)(kt * 64 + j) * HD + dq);
            Kt[(dq + 0) * 65 + j] = kv.x;
            Kt[(dq + 1) * 65 + j] = kv.y;
            Kt[(dq + 2) * 65 + j] = kv.z;
            Kt[(dq + 3) * 65 + j] = kv.w;
            *(float4*)&Vs[j * 64 + dq] =
                *(const float4*)(Vg + (size_t)(kt * 64 + j) * HD + dq);
        }
        __syncthreads();

        // S = Q K^T  (4x4 microtile per thread)
        float s[4][4];
        #pragma unroll
        for (int ii = 0; ii < 4; ii++)
            #pragma unroll
            for (int jj = 0; jj < 4; jj++) s[ii][jj] = 0.f;

        for (int d0 = 0; d0 < 64; d0 += 4) {
            float qa[4][4];
            #pragma unroll
            for (int ii = 0; ii < 4; ii++) {
                float4 qv = *(const float4*)&Qs[(ty + 16 * ii) * 64 + d0];
                qa[ii][0] = qv.x; qa[ii][1] = qv.y; qa[ii][2] = qv.z; qa[ii][3] = qv.w;
            }
            #pragma unroll
            for (int dd = 0; dd < 4; dd++) {
                float kv[4];
                #pragma unroll
                for (int jj = 0; jj < 4; jj++)
                    kv[jj] = Kt[(d0 + dd) * 65 + tx + 16 * jj];
                #pragma unroll
                for (int ii = 0; ii < 4; ii++)
                    #pragma unroll
                    for (int jj = 0; jj < 4; jj++)
                        s[ii][jj] += qa[ii][dd] * kv[jj];
            }
        }

        // online softmax (row reductions across the 16 tx lanes of each ty)
        #pragma unroll
        for (int ii = 0; ii < 4; ii++) {
            float mt = fmaxf(fmaxf(s[ii][0], s[ii][1]), fmaxf(s[ii][2], s[ii][3]));
            #pragma unroll
            for (int w = 8; w >= 1; w >>= 1)
                mt = fmaxf(mt, __shfl_xor_sync(0xffffffffu, mt, w));
            float mnew = fmaxf(m_i[ii], mt);
            float sum = 0.f;
            #pragma unroll
            for (int jj = 0; jj < 4; jj++) {
                float p = __expf(s[ii][jj] - mnew);
                sum += p;
                Ps[(ty + 16 * ii) * 64 + tx + 16 * jj] = p;
            }
            #pragma unroll
            for (int w = 8; w >= 1; w >>= 1)
                sum += __shfl_xor_sync(0xffffffffu, sum, w);
            float sc = __expf(m_i[ii] - mnew);
            l_i[ii] = l_i[ii] * sc + sum;
            m_i[ii] = mnew;
            #pragma unroll
            for (int jj = 0; jj < 4; jj++) o[ii][jj] *= sc;
        }
        __syncwarp();   // Ps producer/consumer are the same warp (same ty group)

        // O += P V
        for (int j0 = 0; j0 < 64; j0 += 4) {
            float pa[4][4];
            #pragma unroll
            for (int ii = 0; ii < 4; ii++) {
                float4 pv = *(const float4*)&Ps[(ty + 16 * ii) * 64 + j0];
                pa[ii][0] = pv.x; pa[ii][1] = pv.y; pa[ii][2] = pv.z; pa[ii][3] = pv.w;
            }
            #pragma unroll
            for (int dj = 0; dj < 4; dj++) {
                float vv[4];
                #pragma unroll
                for (int jj = 0; jj < 4; jj++)
                    vv[jj] = Vs[(j0 + dj) * 64 + tx + 16 * jj];
                #pragma unroll
                for (int ii = 0; ii < 4; ii++)
                    #pragma unroll
                    for (int jj = 0; jj < 4; jj++)
                        o[ii][jj] += pa[ii][dj] * vv[jj];
            }
        }
    }

    // normalize and write to ctx [b,n,c] with c = h*64 + dim
    const int b = bh / NH, h = bh % NH;
    #pragma unroll
    for (int ii = 0; ii < 4; ii++) {
        float inv = 1.f / l_i[ii];
        int n = qt * 64 + ty + 16 * ii;
        float* dst = g_ctx + ((size_t)(b * SEQ + n)) * CDIM + h * HD;
        #pragma unroll
        for (int jj = 0; jj < 4; jj++)
            dst[tx + 16 * jj] = o[ii][jj] * inv;
    }
}

// ---------------------------------------------------------------------------
// Launch
// ---------------------------------------------------------------------------
extern "C" void kernel_launch(void* const* d_in, const int* in_sizes, int n_in,
                              void* d_out, int out_size)
{
    const float* x      = (const float*)d_in[0];   // [B,N,C]
    const float* w_qkv  = (const float*)d_in[1];   // [3C,C]
    const float* w_proj = (const float*)d_in[2];   // [C,C]
    const float* b_proj = (const float*)d_in[3];   // [C]
    float* out = (float*)d_out;                    // [B,N,C]

    // 1) QKV projection -> g_q (scaled), g_k, g_v
    dim3 g1((3 * CDIM) / 128, MTOT / 128);         // (18, 64)
    sgemm_kernel<0><<<g1, 256>>>(x, w_qkv, nullptr, nullptr);

    // 2) attention -> g_ctx
    cudaFuncSetAttribute(attn_kernel,
                         cudaFuncAttributeMaxDynamicSharedMemorySize,
                         ATTN_SMEM_BYTES);
    dim3 g2(SEQ / 64, BATCH * NH);                 // (16, 96)
    attn_kernel<<<g2, 256, ATTN_SMEM_BYTES>>>();

    // 3) output projection + bias -> out
    dim3 g3(CDIM / 128, MTOT / 128);               // (6, 64)
    sgemm_kernel<1><<<g3, 256>>>(x /*ignored*/, w_proj, b_proj, out);
}

// round 10
// speedup vs baseline: 1.2537x; 1.2537x over previous
#include <cuda_runtime.h>
#include <cuda_bf16.h>
#include <math.h>

// Problem constants
#define BATCH 8
#define SEQ   1024
#define CDIM  768
#define NH    12
#define HD    64
#define MTOT  (BATCH*SEQ)          // 8192
#define QK_SCALE 0.125f            // 64^-0.5

// ---------------------------------------------------------------------------
// Scratch (device globals — no allocations allowed)
// ---------------------------------------------------------------------------
__device__ float g_q[BATCH*NH*SEQ*HD];     // [b,h,n,d], pre-scaled by QK_SCALE
__device__ float g_k[BATCH*NH*SEQ*HD];     // [b,h,n,d]
__device__ float g_v[BATCH*NH*SEQ*HD];     // [b,h,n,d]
__device__ float g_ctx[BATCH*SEQ*CDIM];    // [b,n,c] attention output

// ---------------------------------------------------------------------------
// f32x2 packed helpers (FFMA2 path — ptxas won't auto-fuse from C++)
// ---------------------------------------------------------------------------
typedef unsigned long long u64;
__device__ __forceinline__ u64 pack2(float lo, float hi) {
    u64 r; asm("mov.b64 %0, {%1, %2};" : "=l"(r) : "f"(lo), "f"(hi)); return r;
}
__device__ __forceinline__ float2 unpack2(u64 v) {
    float2 o; asm("mov.b64 {%0, %1}, %2;" : "=f"(o.x), "=f"(o.y) : "l"(v)); return o;
}
__device__ __forceinline__ void ffma2(u64 &d, u64 a, u64 b) {
    asm("fma.rn.f32x2 %0, %1, %2, %0;" : "+l"(d) : "l"(a), "l"(b));
}
__device__ __forceinline__ void mul2(u64 &d, u64 a) {
    asm("mul.rn.f32x2 %0, %0, %1;" : "+l"(d) : "l"(a));
}

// ---------------------------------------------------------------------------
// QKV scatter epilogue: f in [0,2304) -> {q,k,v}[b,h,n,d]
// ---------------------------------------------------------------------------
__device__ __forceinline__ void store_qkv(int m, int f, float val) {
    int b = m >> 10, n = m & 1023;
    int which = f / CDIM;
    int rr = f - which * CDIM;
    int h = rr >> 6, d = rr & 63;
    float* dst = (which == 0) ? g_q : (which == 1) ? g_k : g_v;
    if (which == 0) val *= QK_SCALE;            // fold scale into Q
    dst[((size_t)(b * NH + h) * SEQ + n) * HD + d] = val;
}

// ---------------------------------------------------------------------------
// SGEMM: C[m,f] = sum_k A[m,k] * W[f,k]
//   MODE 0: A = x, scatter into g_q/g_k/g_v        (M=8192, N=2304, K=768)
//   MODE 1: A = g_ctx, out = C + bias              (M=8192, N=768,  K=768)
// 128x128x16 tile, 256 threads, 8x8 microtile (split halves 4+4 for
// conflict-free b-reads), f32x2 accumulators, double-buffered smem with
// register prefetch (one __syncthreads per k-tile).
// ---------------------------------------------------------------------------
#define GAP 132   // padded smem pitch (floats); 132*4B = 528B, 16B aligned

template<int MODE>
__global__ __launch_bounds__(256, 2)
void sgemm_kernel(const float* __restrict__ A,
                  const float* __restrict__ W,
                  const float* __restrict__ bias,
                  float* __restrict__ out)
{
    const int K = CDIM;
    __shared__ __align__(16) float As[2][16 * GAP];
    __shared__ __align__(16) float Bs[2][16 * GAP];

    const int tid = threadIdx.x;
    const int m0 = blockIdx.y * 128;
    const int f0 = blockIdx.x * 128;
    const int tx = tid & 15, ty = tid >> 4;

    const float* Ap = (MODE == 0) ? A : g_ctx;

    // prefetch staging
    const int lrow = tid >> 2;            // 0..63 (thread loads rows lrow, lrow+64)
    const int lkq  = (tid & 3) << 2;      // 0,4,8,12
    float4 pA[2], pB[2];

    u64 acc[8][4];
    #pragma unroll
    for (int i = 0; i < 8; i++)
        #pragma unroll
        for (int j = 0; j < 4; j++) acc[i][j] = 0ull;

    // prologue: load tile 0 into buffer 0
    #pragma unroll
    for (int t = 0; t < 2; t++) {
        int row = lrow + (t << 6);
        pA[t] = *(const float4*)(Ap + (size_t)(m0 + row) * K + lkq);
        pB[t] = *(const float4*)(W  + (size_t)(f0 + row) * K + lkq);
    }
    #pragma unroll
    for (int t = 0; t < 2; t++) {
        int row = lrow + (t << 6);
        As[0][(lkq + 0) * GAP + row] = pA[t].x;
        As[0][(lkq + 1) * GAP + row] = pA[t].y;
        As[0][(lkq + 2) * GAP + row] = pA[t].z;
        As[0][(lkq + 3) * GAP + row] = pA[t].w;
        Bs[0][(lkq + 0) * GAP + row] = pB[t].x;
        Bs[0][(lkq + 1) * GAP + row] = pB[t].y;
        Bs[0][(lkq + 2) * GAP + row] = pB[t].z;
        Bs[0][(lkq + 3) * GAP + row] = pB[t].w;
    }
    __syncthreads();

    for (int k0 = 0; k0 < K; k0 += 16) {
        const int cbuf = (k0 >> 4) & 1;
        const int nbuf = cbuf ^ 1;
        const bool more = (k0 + 16) < K;

        // prefetch next tile into registers (overlaps with compute below)
        if (more) {
            #pragma unroll
            for (int t = 0; t < 2; t++) {
                int row = lrow + (t << 6);
                pA[t] = *(const float4*)(Ap + (size_t)(m0 + row) * K + k0 + 16 + lkq);
                pB[t] = *(const float4*)(W  + (size_t)(f0 + row) * K + k0 + 16 + lkq);
            }
        }

        // compute from current buffer
        #pragma unroll
        for (int k = 0; k < 16; k++) {
            // b: consecutive float4s across lanes -> conflict-free, loaded as u64 pairs
            ulonglong2 b0 = *(const ulonglong2*)&Bs[cbuf][k * GAP + 4 * tx];
            ulonglong2 b1 = *(const ulonglong2*)&Bs[cbuf][k * GAP + 64 + 4 * tx];
            // a: per-warp broadcast (2 distinct addresses)
            float4 a0 = *(const float4*)&As[cbuf][k * GAP + 4 * ty];
            float4 a1 = *(const float4*)&As[cbuf][k * GAP + 64 + 4 * ty];
            u64 rb[4] = { b0.x, b0.y, b1.x, b1.y };
            float ra[8] = { a0.x, a0.y, a0.z, a0.w, a1.x, a1.y, a1.z, a1.w };
            #pragma unroll
            for (int i = 0; i < 8; i++) {
                u64 aa = pack2(ra[i], ra[i]);
                #pragma unroll
                for (int j = 0; j < 4; j++) ffma2(acc[i][j], aa, rb[j]);
            }
        }

        // store prefetched tile into the other buffer
        if (more) {
            #pragma unroll
            for (int t = 0; t < 2; t++) {
                int row = lrow + (t << 6);
                As[nbuf][(lkq + 0) * GAP + row] = pA[t].x;
                As[nbuf][(lkq + 1) * GAP + row] = pA[t].y;
                As[nbuf][(lkq + 2) * GAP + row] = pA[t].z;
                As[nbuf][(lkq + 3) * GAP + row] = pA[t].w;
                Bs[nbuf][(lkq + 0) * GAP + row] = pB[t].x;
                Bs[nbuf][(lkq + 1) * GAP + row] = pB[t].y;
                Bs[nbuf][(lkq + 2) * GAP + row] = pB[t].z;
                Bs[nbuf][(lkq + 3) * GAP + row] = pB[t].w;
            }
            __syncthreads();
        }
    }

    // epilogue: rows {4ty+i, 64+4ty+i}, cols {4tx+2j, 64+4tx+2j}
    #pragma unroll
    for (int i = 0; i < 8; i++) {
        int m = m0 + ((i < 4) ? (4 * ty + i) : (64 + 4 * ty + (i - 4)));
        #pragma unroll
        for (int j = 0; j < 4; j++) {
            float2 v = unpack2(acc[i][j]);
            int f = f0 + ((j < 2) ? (4 * tx + 2 * j) : (64 + 4 * tx + 2 * (j - 2)));
            if (MODE == 0) {
                store_qkv(m, f, v.x);
                store_qkv(m, f + 1, v.y);
            } else {
                out[(size_t)m * CDIM + f]     = v.x + bias[f];
                out[(size_t)m * CDIM + f + 1] = v.y + bias[f + 1];
            }
        }
    }
}

// ---------------------------------------------------------------------------
// Flash-style attention, f32x2 packed math. Grid: (SEQ/64, B*H), 256 threads.
// Thread (ty,tx): rows {ty+16*ii}. S-phase cols {tx+16*jj}; PV-phase owns
// output dims {4*tx..4*tx+3}. K/V stored row-major [j][d] pitch 68; packed
// pairs along d are natural ulonglong2 reads (no pack MOVs in S-phase).
// ---------------------------------------------------------------------------
#define KP 68   // K/V smem pitch (floats); 68*4=272B, 16B aligned
#define ATTN_SMEM_FLOATS (64*64 + 64*KP + 64*KP + 64*64)   // 16896
#define ATTN_SMEM_BYTES  (ATTN_SMEM_FLOATS * 4)            // 67584

__global__ __launch_bounds__(256, 2)
void attn_kernel()
{
    extern __shared__ __align__(16) float sm[];
    float* Qs = sm;                  // [64][64]
    float* Ks = Qs + 64 * 64;        // [64][KP]  row-major (j, d)
    float* Vs = Ks + 64 * KP;        // [64][KP]  row-major (j, d)
    float* Ps = Vs + 64 * KP;        // [64][64]

    const int tid = threadIdx.x;
    const int tx = tid & 15, ty = tid >> 4;
    const int bh = blockIdx.y, qt = blockIdx.x;

    const float* Qg = g_q + (size_t)bh * SEQ * HD;
    const float* Kg = g_k + (size_t)bh * SEQ * HD;
    const float* Vg = g_v + (size_t)bh * SEQ * HD;

    // load 64x64 Q tile (already scaled)
    #pragma unroll
    for (int t = 0; t < 4; t++) {
        int l = tid + (t << 8);
        int r = l >> 4, dq = (l & 15) << 2;
        *(float4*)&Qs[r * 64 + dq] =
            *(const float4*)(Qg + (size_t)(qt * 64 + r) * HD + dq);
    }

    float m_i[4], l_i[4];
    u64 o2[4][2];                    // packed output accumulators along d
    #pragma unroll
    for (int ii = 0; ii < 4; ii++) {
        m_i[ii] = -INFINITY; l_i[ii] = 0.f;
        o2[ii][0] = 0ull; o2[ii][1] = 0ull;
    }

    for (int kt = 0; kt < SEQ / 64; kt++) {
        __syncthreads();   // covers Q-load on kt=0, protects Ks/Vs reuse

        // load K/V tiles row-major (coalesced, conflict-free)
        #pragma unroll
        for (int t = 0; t < 4; t++) {
            int l = tid + (t << 8);
            int j = l >> 4, dq = (l & 15) << 2;
            *(float4*)&Ks[j * KP + dq] =
                *(const float4*)(Kg + (size_t)(kt * 64 + j) * HD + dq);
            *(float4*)&Vs[j * KP + dq] =
                *(const float4*)(Vg + (size_t)(kt * 64 + j) * HD + dq);
        }
        __syncthreads();

        // S = Q K^T — packed pairs along d (both operands natural pairs)
        u64 s2[4][4];
        #pragma unroll
        for (int ii = 0; ii < 4; ii++)
            #pragma unroll
            for (int jj = 0; jj < 4; jj++) s2[ii][jj] = 0ull;

        for (int d0 = 0; d0 < 64; d0 += 4) {
            ulonglong2 q2[4];
            #pragma unroll
            for (int ii = 0; ii < 4; ii++)
                q2[ii] = *(const ulonglong2*)&Qs[(ty + 16 * ii) * 64 + d0];
            #pragma unroll
            for (int jj = 0; jj < 4; jj++) {
                ulonglong2 k2 = *(const ulonglong2*)&Ks[(tx + 16 * jj) * KP + d0];
                #pragma unroll
                for (int ii = 0; ii < 4; ii++) {
                    ffma2(s2[ii][jj], q2[ii].x, k2.x);
                    ffma2(s2[ii][jj], q2[ii].y, k2.y);
                }
            }
        }

        // horizontal finish
        float s[4][4];
        #pragma unroll
        for (int ii = 0; ii < 4; ii++)
            #pragma unroll
            for (int jj = 0; jj < 4; jj++) {
                float2 v = unpack2(s2[ii][jj]);
                s[ii][jj] = v.x + v.y;
            }

        // online softmax (row reductions across the 16 tx lanes of each ty)
        #pragma unroll
        for (int ii = 0; ii < 4; ii++) {
            float mt = fmaxf(fmaxf(s[ii][0], s[ii][1]), fmaxf(s[ii][2], s[ii][3]));
            #pragma unroll
            for (int w = 8; w >= 1; w >>= 1)
                mt = fmaxf(mt, __shfl_xor_sync(0xffffffffu, mt, w));
            float mnew = fmaxf(m_i[ii], mt);
            float sum = 0.f;
            #pragma unroll
            for (int jj = 0; jj < 4; jj++) {
                float p = __expf(s[ii][jj] - mnew);
                sum += p;
                Ps[(ty + 16 * ii) * 64 + tx + 16 * jj] = p;
            }
            #pragma unroll
            for (int w = 8; w >= 1; w >>= 1)
                sum += __shfl_xor_sync(0xffffffffu, sum, w);
            float sc = __expf(m_i[ii] - mnew);
            l_i[ii] = l_i[ii] * sc + sum;
            m_i[ii] = mnew;
            u64 sc2 = pack2(sc, sc);
            mul2(o2[ii][0], sc2);
            mul2(o2[ii][1], sc2);
        }
        __syncwarp();   // Ps producer/consumer share a warp (same ty group)

        // O += P V  (packed pairs along d; P broadcast per (ii,j))
        for (int j0 = 0; j0 < 64; j0 += 4) {
            float pa[4][4];
            #pragma unroll
            for (int ii = 0; ii < 4; ii++) {
                float4 pv = *(const float4*)&Ps[(ty + 16 * ii) * 64 + j0];
                pa[ii][0] = pv.x; pa[ii][1] = pv.y; pa[ii][2] = pv.z; pa[ii][3] = pv.w;
            }
            #pragma unroll
            for (int dj = 0; dj < 4; dj++) {
                ulonglong2 v2 = *(const ulonglong2*)&Vs[(j0 + dj) * KP + 4 * tx];
                #pragma unroll
                for (int ii = 0; ii < 4; ii++) {
                    u64 pd = pack2(pa[ii][dj], pa[ii][dj]);
                    ffma2(o2[ii][0], pd, v2.x);
                    ffma2(o2[ii][1], pd, v2.y);
                }
            }
        }
    }

    // normalize and write to ctx [b,n,c]; thread owns dims 4tx..4tx+3
    const int b = bh / NH, h = bh % NH;
    #pragma unroll
    for (int ii = 0; ii < 4; ii++) {
        float inv = 1.f / l_i[ii];
        int n = qt * 64 + ty + 16 * ii;
        float* dst = g_ctx + ((size_t)(b * SEQ + n)) * CDIM + h * HD;
        float2 lo = unpack2(o2[ii][0]);
        float2 hi = unpack2(o2[ii][1]);
        float4 ov = { lo.x * inv, lo.y * inv, hi.x * inv, hi.y * inv };
        *(float4*)(dst + 4 * tx) = ov;
    }
}

// ---------------------------------------------------------------------------
// Launch
// ---------------------------------------------------------------------------
extern "C" void kernel_launch(void* const* d_in, const int* in_sizes, int n_in,
                              void* d_out, int out_size)
{
    const float* x      = (const float*)d_in[0];   // [B,N,C]
    const float* w_qkv  = (const float*)d_in[1];   // [3C,C]
    const float* w_proj = (const float*)d_in[2];   // [C,C]
    const float* b_proj = (const float*)d_in[3];   // [C]
    float* out = (float*)d_out;                    // [B,N,C]

    // 1) QKV projection -> g_q (scaled), g_k, g_v
    dim3 g1((3 * CDIM) / 128, MTOT / 128);         // (18, 64)
    sgemm_kernel<0><<<g1, 256>>>(x, w_qkv, nullptr, nullptr);

    // 2) attention -> g_ctx
    cudaFuncSetAttribute(attn_kernel,
                         cudaFuncAttributeMaxDynamicSharedMemorySize,
                         ATTN_SMEM_BYTES);
    dim3 g2(SEQ / 64, BATCH * NH);                 // (16, 96)
    attn_kernel<<<g2, 256, ATTN_SMEM_BYTES>>>();

    // 3) output projection + bias -> out
    dim3 g3(CDIM / 128, MTOT / 128);               // (6, 64)
    sgemm_kernel<1><<<g3, 256>>>(x /*ignored*/, w_proj, b_proj, out);
}

// round 11
// speedup vs baseline: 1.2541x; 1.0003x over previous
#include <cuda_runtime.h>
#include <cuda_bf16.h>
#include <math.h>

// Problem constants
#define BATCH 8
#define SEQ   1024
#define CDIM  768
#define NH    12
#define HD    64
#define MTOT  (BATCH*SEQ)          // 8192
#define QK_SCALE 0.125f            // 64^-0.5

// ---------------------------------------------------------------------------
// Scratch (device globals — no allocations allowed)
// ---------------------------------------------------------------------------
__device__ float g_q[BATCH*NH*SEQ*HD];     // [b,h,n,d], pre-scaled by QK_SCALE
__device__ float g_k[BATCH*NH*SEQ*HD];     // [b,h,n,d]
__device__ float g_v[BATCH*NH*SEQ*HD];     // [b,h,n,d]
__device__ float g_ctx[BATCH*SEQ*CDIM];    // [b,n,c] attention output

// ---------------------------------------------------------------------------
// f32x2 packed helpers (FFMA2 path — ptxas won't auto-fuse from C++)
// ---------------------------------------------------------------------------
typedef unsigned long long u64;
__device__ __forceinline__ u64 pack2(float lo, float hi) {
    u64 r; asm("mov.b64 %0, {%1, %2};" : "=l"(r) : "f"(lo), "f"(hi)); return r;
}
__device__ __forceinline__ float2 unpack2(u64 v) {
    float2 o; asm("mov.b64 {%0, %1}, %2;" : "=f"(o.x), "=f"(o.y) : "l"(v)); return o;
}
__device__ __forceinline__ void ffma2(u64 &d, u64 a, u64 b) {
    asm("fma.rn.f32x2 %0, %1, %2, %0;" : "+l"(d) : "l"(a), "l"(b));
}
__device__ __forceinline__ void mul2(u64 &d, u64 a) {
    asm("mul.rn.f32x2 %0, %0, %1;" : "+l"(d) : "l"(a));
}

// ---------------------------------------------------------------------------
// QKV scatter epilogue: f in [0,2304) -> {q,k,v}[b,h,n,d]
// ---------------------------------------------------------------------------
__device__ __forceinline__ void store_qkv(int m, int f, float val) {
    int b = m >> 10, n = m & 1023;
    int which = f / CDIM;
    int rr = f - which * CDIM;
    int h = rr >> 6, d = rr & 63;
    float* dst = (which == 0) ? g_q : (which == 1) ? g_k : g_v;
    if (which == 0) val *= QK_SCALE;            // fold scale into Q
    dst[((size_t)(b * NH + h) * SEQ + n) * HD + d] = val;
}

// ---------------------------------------------------------------------------
// SGEMM: C[m,f] = sum_k A[m,k] * W[f,k]
//   MODE 0: A = x, scatter into g_q/g_k/g_v        (M=8192, N=2304, K=768)
//   MODE 1: A = g_ctx, out = C + bias              (M=8192, N=768,  K=768)
// 128x128x16 tile, 256 threads, 8x8 microtile (split halves 4+4 for
// conflict-free b-reads), f32x2 accumulators, double-buffered smem with
// register prefetch (one __syncthreads per k-tile).
// ---------------------------------------------------------------------------
#define GAP 132   // padded smem pitch (floats); 132*4B = 528B, 16B aligned

template<int MODE>
__global__ __launch_bounds__(256, 2)
void sgemm_kernel(const float* __restrict__ A,
                  const float* __restrict__ W,
                  const float* __restrict__ bias,
                  float* __restrict__ out)
{
    const int K = CDIM;
    __shared__ __align__(16) float As[2][16 * GAP];
    __shared__ __align__(16) float Bs[2][16 * GAP];

    const int tid = threadIdx.x;
    const int m0 = blockIdx.y * 128;
    const int f0 = blockIdx.x * 128;
    const int tx = tid & 15, ty = tid >> 4;

    const float* Ap = (MODE == 0) ? A : g_ctx;

    // prefetch staging
    const int lrow = tid >> 2;            // 0..63 (thread loads rows lrow, lrow+64)
    const int lkq  = (tid & 3) << 2;      // 0,4,8,12
    float4 pA[2], pB[2];

    u64 acc[8][4];
    #pragma unroll
    for (int i = 0; i < 8; i++)
        #pragma unroll
        for (int j = 0; j < 4; j++) acc[i][j] = 0ull;

    // prologue: load tile 0 into buffer 0
    #pragma unroll
    for (int t = 0; t < 2; t++) {
        int row = lrow + (t << 6);
        pA[t] = *(const float4*)(Ap + (size_t)(m0 + row) * K + lkq);
        pB[t] = *(const float4*)(W  + (size_t)(f0 + row) * K + lkq);
    }
    #pragma unroll
    for (int t = 0; t < 2; t++) {
        int row = lrow + (t << 6);
        As[0][(lkq + 0) * GAP + row] = pA[t].x;
        As[0][(lkq + 1) * GAP + row] = pA[t].y;
        As[0][(lkq + 2) * GAP + row] = pA[t].z;
        As[0][(lkq + 3) * GAP + row] = pA[t].w;
        Bs[0][(lkq + 0) * GAP + row] = pB[t].x;
        Bs[0][(lkq + 1) * GAP + row] = pB[t].y;
        Bs[0][(lkq + 2) * GAP + row] = pB[t].z;
        Bs[0][(lkq + 3) * GAP + row] = pB[t].w;
    }
    __syncthreads();

    for (int k0 = 0; k0 < K; k0 += 16) {
        const int cbuf = (k0 >> 4) & 1;
        const int nbuf = cbuf ^ 1;
        const bool more = (k0 + 16) < K;

        // prefetch next tile into registers (overlaps with compute below)
        if (more) {
            #pragma unroll
            for (int t = 0; t < 2; t++) {
                int row = lrow + (t << 6);
                pA[t] = *(const float4*)(Ap + (size_t)(m0 + row) * K + k0 + 16 + lkq);
                pB[t] = *(const float4*)(W  + (size_t)(f0 + row) * K + k0 + 16 + lkq);
            }
        }

        // compute from current buffer
        #pragma unroll
        for (int k = 0; k < 16; k++) {
            // b: consecutive float4s across lanes -> conflict-free, loaded as u64 pairs
            ulonglong2 b0 = *(const ulonglong2*)&Bs[cbuf][k * GAP + 4 * tx];
            ulonglong2 b1 = *(const ulonglong2*)&Bs[cbuf][k * GAP + 64 + 4 * tx];
            // a: per-warp broadcast (2 distinct addresses)
            float4 a0 = *(const float4*)&As[cbuf][k * GAP + 4 * ty];
            float4 a1 = *(const float4*)&As[cbuf][k * GAP + 64 + 4 * ty];
            u64 rb[4] = { b0.x, b0.y, b1.x, b1.y };
            float ra[8] = { a0.x, a0.y, a0.z, a0.w, a1.x, a1.y, a1.z, a1.w };
            #pragma unroll
            for (int i = 0; i < 8; i++) {
                u64 aa = pack2(ra[i], ra[i]);
                #pragma unroll
                for (int j = 0; j < 4; j++) ffma2(acc[i][j], aa, rb[j]);
            }
        }

        // store prefetched tile into the other buffer
        if (more) {
            #pragma unroll
            for (int t = 0; t < 2; t++) {
                int row = lrow + (t << 6);
                As[nbuf][(lkq + 0) * GAP + row] = pA[t].x;
                As[nbuf][(lkq + 1) * GAP + row] = pA[t].y;
                As[nbuf][(lkq + 2) * GAP + row] = pA[t].z;
                As[nbuf][(lkq + 3) * GAP + row] = pA[t].w;
                Bs[nbuf][(lkq + 0) * GAP + row] = pB[t].x;
                Bs[nbuf][(lkq + 1) * GAP + row] = pB[t].y;
                Bs[nbuf][(lkq + 2) * GAP + row] = pB[t].z;
                Bs[nbuf][(lkq + 3) * GAP + row] = pB[t].w;
            }
            __syncthreads();
        }
    }

    // epilogue: rows {4ty+i, 64+4ty+i}, cols {4tx+2j, 64+4tx+2j}
    #pragma unroll
    for (int i = 0; i < 8; i++) {
        int m = m0 + ((i < 4) ? (4 * ty + i) : (64 + 4 * ty + (i - 4)));
        #pragma unroll
        for (int j = 0; j < 4; j++) {
            float2 v = unpack2(acc[i][j]);
            int f = f0 + ((j < 2) ? (4 * tx + 2 * j) : (64 + 4 * tx + 2 * (j - 2)));
            if (MODE == 0) {
                store_qkv(m, f, v.x);
                store_qkv(m, f + 1, v.y);
            } else {
                out[(size_t)m * CDIM + f]     = v.x + bias[f];
                out[(size_t)m * CDIM + f + 1] = v.y + bias[f + 1];
            }
        }
    }
}

// ---------------------------------------------------------------------------
// Flash-style attention, f32x2 packed math. Grid: (SEQ/64, B*H), 256 threads.
// Thread (ty,tx): rows {ty+16*ii}. S-phase cols {tx+16*jj}; PV-phase owns
// output dims {4*tx..4*tx+3}. K/V stored row-major [j][d] pitch 68; packed
// pairs along d are natural ulonglong2 reads (no pack MOVs in S-phase).
// ---------------------------------------------------------------------------
#define KP 68   // K/V smem pitch (floats); 68*4=272B, 16B aligned
#define ATTN_SMEM_FLOATS (64*64 + 64*KP + 64*KP + 64*64)   // 16896
#define ATTN_SMEM_BYTES  (ATTN_SMEM_FLOATS * 4)            // 67584

__global__ __launch_bounds__(256, 2)
void attn_kernel()
{
    extern __shared__ __align__(16) float sm[];
    float* Qs = sm;                  // [64][64]
    float* Ks = Qs + 64 * 64;        // [64][KP]  row-major (j, d)
    float* Vs = Ks + 64 * KP;        // [64][KP]  row-major (j, d)
    float* Ps = Vs + 64 * KP;        // [64][64]

    const int tid = threadIdx.x;
    const int tx = tid & 15, ty = tid >> 4;
    const int bh = blockIdx.y, qt = blockIdx.x;

    const float* Qg = g_q + (size_t)bh * SEQ * HD;
    const float* Kg = g_k + (size_t)bh * SEQ * HD;
    const float* Vg = g_v + (size_t)bh * SEQ * HD;

    // load 64x64 Q tile (already scaled)
    #pragma unroll
    for (int t = 0; t < 4; t++) {
        int l = tid + (t << 8);
        int r = l >> 4, dq = (l & 15) << 2;
        *(float4*)&Qs[r * 64 + dq] =
            *(const float4*)(Qg + (size_t)(qt * 64 + r) * HD + dq);
    }

    float m_i[4], l_i[4];
    u64 o2[4][2];                    // packed output accumulators along d
    #pragma unroll
    for (int ii = 0; ii < 4; ii++) {
        m_i[ii] = -INFINITY; l_i[ii] = 0.f;
        o2[ii][0] = 0ull; o2[ii][1] = 0ull;
    }

    for (int kt = 0; kt < SEQ / 64; kt++) {
        __syncthreads();   // covers Q-load on kt=0, protects Ks/Vs reuse

        // load K/V tiles row-major (coalesced, conflict-free)
        #pragma unroll
        for (int t = 0; t < 4; t++) {
            int l = tid + (t << 8);
            int j = l >> 4, dq = (l & 15) << 2;
            *(float4*)&Ks[j * KP + dq] =
                *(const float4*)(Kg + (size_t)(kt * 64 + j) * HD + dq);
            *(float4*)&Vs[j * KP + dq] =
                *(const float4*)(Vg + (size_t)(kt * 64 + j) * HD + dq);
        }
        __syncthreads();

        // S = Q K^T — packed pairs along d (both operands natural pairs)
        u64 s2[4][4];
        #pragma unroll
        for (int ii = 0; ii < 4; ii++)
            #pragma unroll
            for (int jj = 0; jj < 4; jj++) s2[ii][jj] = 0ull;

        for (int d0 = 0; d0 < 64; d0 += 4) {
            ulonglong2 q2[4];
            #pragma unroll
            for (int ii = 0; ii < 4; ii++)
                q2[ii] = *(const ulonglong2*)&Qs[(ty + 16 * ii) * 64 + d0];
            #pragma unroll
            for (int jj = 0; jj < 4; jj++) {
                ulonglong2 k2 = *(const ulonglong2*)&Ks[(tx + 16 * jj) * KP + d0];
                #pragma unroll
                for (int ii = 0; ii < 4; ii++) {
                    ffma2(s2[ii][jj], q2[ii].x, k2.x);
                    ffma2(s2[ii][jj], q2[ii].y, k2.y);
                }
            }
        }

        // horizontal finish
        float s[4][4];
        #pragma unroll
        for (int ii = 0; ii < 4; ii++)
            #pragma unroll
            for (int jj = 0; jj < 4; jj++) {
                float2 v = unpack2(s2[ii][jj]);
                s[ii][jj] = v.x + v.y;
            }

        // online softmax (row reductions across the 16 tx lanes of each ty)
        #pragma unroll
        for (int ii = 0; ii < 4; ii++) {
            float mt = fmaxf(fmaxf(s[ii][0], s[ii][1]), fmaxf(s[ii][2], s[ii][3]));
            #pragma unroll
            for (int w = 8; w >= 1; w >>= 1)
                mt = fmaxf(mt, __shfl_xor_sync(0xffffffffu, mt, w));
            float mnew = fmaxf(m_i[ii], mt);
            float sum = 0.f;
            #pragma unroll
            for (int jj = 0; jj < 4; jj++) {
                float p = __expf(s[ii][jj] - mnew);
                sum += p;
                Ps[(ty + 16 * ii) * 64 + tx + 16 * jj] = p;
            }
            #pragma unroll
            for (int w = 8; w >= 1; w >>= 1)
                sum += __shfl_xor_sync(0xffffffffu, sum, w);
            float sc = __expf(m_i[ii] - mnew);
            l_i[ii] = l_i[ii] * sc + sum;
            m_i[ii] = mnew;
            u64 sc2 = pack2(sc, sc);
            mul2(o2[ii][0], sc2);
            mul2(o2[ii][1], sc2);
        }
        __syncwarp();   // Ps producer/consumer share a warp (same ty group)

        // O += P V  (packed pairs along d; P broadcast per (ii,j))
        for (int j0 = 0; j0 < 64; j0 += 4) {
            float pa[4][4];
            #pragma unroll
            for (int ii = 0; ii < 4; ii++) {
                float4 pv = *(const float4*)&Ps[(ty + 16 * ii) * 64 + j0];
                pa[ii][0] = pv.x; pa[ii][1] = pv.y; pa[ii][2] = pv.z; pa[ii][3] = pv.w;
            }
            #pragma unroll
            for (int dj = 0; dj < 4; dj++) {
                ulonglong2 v2 = *(const ulonglong2*)&Vs[(j0 + dj) * KP + 4 * tx];
                #pragma unroll
                for (int ii = 0; ii < 4; ii++) {
                    u64 pd = pack2(pa[ii][dj], pa[ii][dj]);
                    ffma2(o2[ii][0], pd, v2.x);
                    ffma2(o2[ii][1], pd, v2.y);
                }
            }
        }
    }

    // normalize and write to ctx [b,n,c]; thread owns dims 4tx..4tx+3
    const int b = bh / NH, h = bh % NH;
    #pragma unroll
    for (int ii = 0; ii < 4; ii++) {
        float inv = 1.f / l_i[ii];
        int n = qt * 64 + ty + 16 * ii;
        float* dst = g_ctx + ((size_t)(b * SEQ + n)) * CDIM + h * HD;
        float2 lo = unpack2(o2[ii][0]);
        float2 hi = unpack2(o2[ii][1]);
        float4 ov = { lo.x * inv, lo.y * inv, hi.x * inv, hi.y * inv };
        *(float4*)(dst + 4 * tx) = ov;
    }
}

// ---------------------------------------------------------------------------
// Launch
// ---------------------------------------------------------------------------
extern "C" void kernel_launch(void* const* d_in, const int* in_sizes, int n_in,
                              void* d_out, int out_size)
{
    const float* x      = (const float*)d_in[0];   // [B,N,C]
    const float* w_qkv  = (const float*)d_in[1];   // [3C,C]
    const float* w_proj = (const float*)d_in[2];   // [C,C]
    const float* b_proj = (const float*)d_in[3];   // [C]
    float* out = (float*)d_out;                    // [B,N,C]

    // 1) QKV projection -> g_q (scaled), g_k, g_v
    dim3 g1((3 * CDIM) / 128, MTOT / 128);         // (18, 64)
    sgemm_kernel<0><<<g1, 256>>>(x, w_qkv, nullptr, nullptr);

    // 2) attention -> g_ctx
    cudaFuncSetAttribute(attn_kernel,
                         cudaFuncAttributeMaxDynamicSharedMemorySize,
                         ATTN_SMEM_BYTES);
    dim3 g2(SEQ / 64, BATCH * NH);                 // (16, 96)
    attn_kernel<<<g2, 256, ATTN_SMEM_BYTES>>>();

    // 3) output projection + bias -> out
    dim3 g3(CDIM / 128, MTOT / 128);               // (6, 64)
    sgemm_kernel<1><<<g3, 256>>>(x /*ignored*/, w_proj, b_proj, out);
}

// round 13
// speedup vs baseline: 1.2637x; 1.0077x over previous
#include <cuda_runtime.h>
#include <cuda_bf16.h>
#include <math.h>
#include <cstdint>

// Problem constants
#define BATCH 8
#define SEQ   1024
#define CDIM  768
#define NH    12
#define HD    64
#define MTOT  (BATCH*SEQ)          // 8192
// QK scale with log2(e) folded in: softmax computed in exp2 domain
#define QK_SCALE_LOG2E 0.1803368801111204f   // 0.125 * 1.4426950408889634

// ---------------------------------------------------------------------------
// Scratch (device globals — no allocations allowed)
// ---------------------------------------------------------------------------
__device__ float g_q[BATCH*NH*SEQ*HD];     // [b,h,n,d], pre-scaled by QK_SCALE*log2e
__device__ float g_k[BATCH*NH*SEQ*HD];     // [b,h,n,d]
__device__ float g_v[BATCH*NH*SEQ*HD];     // [b,h,n,d]
__device__ float g_ctx[BATCH*SEQ*CDIM];    // [b,n,c] attention output

// ---------------------------------------------------------------------------
// f32x2 packed helpers (FFMA2 path — ptxas won't auto-fuse from C++)
// ---------------------------------------------------------------------------
typedef unsigned long long u64;
__device__ __forceinline__ u64 pack2(float lo, float hi) {
    u64 r; asm("mov.b64 %0, {%1, %2};" : "=l"(r) : "f"(lo), "f"(hi)); return r;
}
__device__ __forceinline__ float2 unpack2(u64 v) {
    float2 o; asm("mov.b64 {%0, %1}, %2;" : "=f"(o.x), "=f"(o.y) : "l"(v)); return o;
}
__device__ __forceinline__ void ffma2(u64 &d, u64 a, u64 b) {
    asm("fma.rn.f32x2 %0, %1, %2, %0;" : "+l"(d) : "l"(a), "l"(b));
}
__device__ __forceinline__ void mul2(u64 &d, u64 a) {
    asm("mul.rn.f32x2 %0, %0, %1;" : "+l"(d) : "l"(a));
}
__device__ __forceinline__ float fast_exp2(float x) {
    float y; asm("ex2.approx.f32 %0, %1;" : "=f"(y) : "f"(x)); return y;
}

// cp.async helpers (sm_80+ PTX — no arch-accelerated features required)
__device__ __forceinline__ uint32_t smem_u32(const void* p) {
    uint32_t a;
    asm("{ .reg .u64 t; cvta.to.shared.u64 t, %1; cvt.u32.u64 %0, t; }"
        : "=r"(a) : "l"(p));
    return a;
}
__device__ __forceinline__ void cp_async16(uint32_t dst, const void* src) {
    asm volatile("cp.async.ca.shared.global [%0], [%1], 16;"
                 :: "r"(dst), "l"(src));
}
#define CP_COMMIT() asm volatile("cp.async.commit_group;" ::: "memory")
#define CP_WAIT0()  asm volatile("cp.async.wait_group 0;"  ::: "memory")

// ---------------------------------------------------------------------------
// QKV scatter epilogue (paired): f even, pair never crosses a 64-boundary
// ---------------------------------------------------------------------------
__device__ __forceinline__ void store_qkv2(int m, int f, float vx, float vy) {
    int b = m >> 10, n = m & 1023;
    int which = f / CDIM;
    int rr = f - which * CDIM;
    int h = rr >> 6, d = rr & 63;
    float* dst = (which == 0) ? g_q : (which == 1) ? g_k : g_v;
    if (which == 0) { vx *= QK_SCALE_LOG2E; vy *= QK_SCALE_LOG2E; }
    float2 v = { vx, vy };
    *(float2*)&dst[((size_t)(b * NH + h) * SEQ + n) * HD + d] = v;
}

// ---------------------------------------------------------------------------
// SGEMM: C[m,f] = sum_k A[m,k] * W[f,k]
//   MODE 0: A = x, scatter into g_q/g_k/g_v        (M=8192, N=2304, K=768)
//   MODE 1: A = g_ctx, out = C + bias              (M=8192, N=768,  K=768)
// 128x128x16 tile, 256 threads, 8x8 microtile (split halves 4+4 for
// conflict-free b-reads), f32x2 accumulators, double-buffered smem with
// register prefetch (one __syncthreads per k-tile).
// ---------------------------------------------------------------------------
#define GAP 132   // padded smem pitch (floats)

template<int MODE>
__global__ __launch_bounds__(256, 2)
void sgemm_kernel(const float* __restrict__ A,
                  const float* __restrict__ W,
                  const float* __restrict__ bias,
                  float* __restrict__ out)
{
    const int K = CDIM;
    __shared__ __align__(16) float As[2][16 * GAP];
    __shared__ __align__(16) float Bs[2][16 * GAP];

    const int tid = threadIdx.x;
    const int m0 = blockIdx.y * 128;
    const int f0 = blockIdx.x * 128;
    const int tx = tid & 15, ty = tid >> 4;

    const float* Ap = (MODE == 0) ? A : g_ctx;

    const int lrow = tid >> 2;            // 0..63 (thread loads rows lrow, lrow+64)
    const int lkq  = (tid & 3) << 2;      // 0,4,8,12
    float4 pA[2], pB[2];

    u64 acc[8][4];
    #pragma unroll
    for (int i = 0; i < 8; i++)
        #pragma unroll
        for (int j = 0; j < 4; j++) acc[i][j] = 0ull;

    // prologue: load tile 0 into buffer 0
    #pragma unroll
    for (int t = 0; t < 2; t++) {
        int row = lrow + (t << 6);
        pA[t] = *(const float4*)(Ap + (size_t)(m0 + row) * K + lkq);
        pB[t] = *(const float4*)(W  + (size_t)(f0 + row) * K + lkq);
    }
    #pragma unroll
    for (int t = 0; t < 2; t++) {
        int row = lrow + (t << 6);
        As[0][(lkq + 0) * GAP + row] = pA[t].x;
        As[0][(lkq + 1) * GAP + row] = pA[t].y;
        As[0][(lkq + 2) * GAP + row] = pA[t].z;
        As[0][(lkq + 3) * GAP + row] = pA[t].w;
        Bs[0][(lkq + 0) * GAP + row] = pB[t].x;
        Bs[0][(lkq + 1) * GAP + row] = pB[t].y;
        Bs[0][(lkq + 2) * GAP + row] = pB[t].z;
        Bs[0][(lkq + 3) * GAP + row] = pB[t].w;
    }
    __syncthreads();

    for (int k0 = 0; k0 < K; k0 += 16) {
        const int cbuf = (k0 >> 4) & 1;
        const int nbuf = cbuf ^ 1;
        const bool more = (k0 + 16) < K;

        if (more) {
            #pragma unroll
            for (int t = 0; t < 2; t++) {
                int row = lrow + (t << 6);
                pA[t] = *(const float4*)(Ap + (size_t)(m0 + row) * K + k0 + 16 + lkq);
                pB[t] = *(const float4*)(W  + (size_t)(f0 + row) * K + k0 + 16 + lkq);
            }
        }

        #pragma unroll
        for (int k = 0; k < 16; k++) {
            ulonglong2 b0 = *(const ulonglong2*)&Bs[cbuf][k * GAP + 4 * tx];
            ulonglong2 b1 = *(const ulonglong2*)&Bs[cbuf][k * GAP + 64 + 4 * tx];
            float4 a0 = *(const float4*)&As[cbuf][k * GAP + 4 * ty];
            float4 a1 = *(const float4*)&As[cbuf][k * GAP + 64 + 4 * ty];
            u64 rb[4] = { b0.x, b0.y, b1.x, b1.y };
            float ra[8] = { a0.x, a0.y, a0.z, a0.w, a1.x, a1.y, a1.z, a1.w };
            #pragma unroll
            for (int i = 0; i < 8; i++) {
                u64 aa = pack2(ra[i], ra[i]);
                #pragma unroll
                for (int j = 0; j < 4; j++) ffma2(acc[i][j], aa, rb[j]);
            }
        }

        if (more) {
            #pragma unroll
            for (int t = 0; t < 2; t++) {
                int row = lrow + (t << 6);
                As[nbuf][(lkq + 0) * GAP + row] = pA[t].x;
                As[nbuf][(lkq + 1) * GAP + row] = pA[t].y;
                As[nbuf][(lkq + 2) * GAP + row] = pA[t].z;
                As[nbuf][(lkq + 3) * GAP + row] = pA[t].w;
                Bs[nbuf][(lkq + 0) * GAP + row] = pB[t].x;
                Bs[nbuf][(lkq + 1) * GAP + row] = pB[t].y;
                Bs[nbuf][(lkq + 2) * GAP + row] = pB[t].z;
                Bs[nbuf][(lkq + 3) * GAP + row] = pB[t].w;
            }
            __syncthreads();
        }
    }

    // epilogue: rows {4ty+i, 64+4ty+i}, col pairs {4tx+2j, 64+4tx+2(j-2)}
    #pragma unroll
    for (int i = 0; i < 8; i++) {
        int m = m0 + ((i < 4) ? (4 * ty + i) : (64 + 4 * ty + (i - 4)));
        #pragma unroll
        for (int j = 0; j < 4; j++) {
            float2 v = unpack2(acc[i][j]);
            int f = f0 + ((j < 2) ? (4 * tx + 2 * j) : (64 + 4 * tx + 2 * (j - 2)));
            if (MODE == 0) {
                store_qkv2(m, f, v.x, v.y);
            } else {
                float2 o = { v.x + bias[f], v.y + bias[f + 1] };
                *(float2*)&out[(size_t)m * CDIM + f] = o;
            }
        }
    }
}

// ---------------------------------------------------------------------------
// Flash-style attention, f32x2 packed math, cp.async double-buffered K/V.
// Grid: (SEQ/64, B*H), 256 threads. Thread (ty,tx): rows {ty+16*ii};
// S-phase cols {tx+16*jj}; PV-phase dims {4*tx..4*tx+3}.
// Softmax runs in exp2 domain (log2e folded into Q scale).
// smem: Qs[64*64] + Ks[2][64*KP] + Vs[2][64*KP] + Ps[64*64]
// ---------------------------------------------------------------------------
#define KP 68                                  // K/V smem pitch (floats)
#define KVB (64 * KP)                          // one K or V buffer (floats)
#define ATTN_SMEM_FLOATS (64*64 + 2*KVB + 2*KVB + 64*64)   // 25600
#define ATTN_SMEM_BYTES  (ATTN_SMEM_FLOATS * 4)            // 102400

__global__ __launch_bounds__(256, 2)
void attn_kernel()
{
    extern __shared__ __align__(16) float sm[];
    float* Qs = sm;                      // [64][64]
    float* Ks = Qs + 64 * 64;            // [2][64][KP]
    float* Vs = Ks + 2 * KVB;            // [2][64][KP]
    float* Ps = Vs + 2 * KVB;            // [64][64]
    const uint32_t sb = smem_u32(sm);
    const uint32_t ks_b = sb + (64 * 64) * 4;
    const uint32_t vs_b = ks_b + 2 * KVB * 4;

    const int tid = threadIdx.x;
    const int tx = tid & 15, ty = tid >> 4;
    const int bh = blockIdx.y, qt = blockIdx.x;

    const float* Qg = g_q + (size_t)bh * SEQ * HD;
    const float* Kg = g_k + (size_t)bh * SEQ * HD;
    const float* Vg = g_v + (size_t)bh * SEQ * HD;

    // per-thread copy coordinates (4 chunks of 16B each for K and V)
    // chunk t: row j = (tid + t*256)>>4, dq = ((tid + t*256)&15)<<2

    // prologue: issue tile 0 into buffer 0
    #pragma unroll
    for (int t = 0; t < 4; t++) {
        int l = tid + (t << 8);
        int j = l >> 4, dq = (l & 15) << 2;
        uint32_t off = (uint32_t)(j * KP + dq) * 4;
        cp_async16(ks_b + off, Kg + (size_t)j * HD + dq);
        cp_async16(vs_b + off, Vg + (size_t)j * HD + dq);
    }
    CP_COMMIT();

    // load 64x64 Q tile (already scaled by QK_SCALE*log2e)
    #pragma unroll
    for (int t = 0; t < 4; t++) {
        int l = tid + (t << 8);
        int r = l >> 4, dq = (l & 15) << 2;
        *(float4*)&Qs[r * 64 + dq] =
            *(const float4*)(Qg + (size_t)(qt * 64 + r) * HD + dq);
    }

    float m_i[4], l_i[4];
    u64 o2[4][2];
    #pragma unroll
    for (int ii = 0; ii < 4; ii++) {
        m_i[ii] = -INFINITY; l_i[ii] = 0.f;
        o2[ii][0] = 0ull; o2[ii][1] = 0ull;
    }

    for (int kt = 0; kt < SEQ / 64; kt++) {
        const int cur = kt & 1;
        CP_WAIT0();          // my copies for tile kt complete
        __syncthreads();     // everyone's copies visible; prev reads of other buf done

        // issue next tile into the other buffer (overlaps with compute below)
        if (kt + 1 < SEQ / 64) {
            const int nxt = cur ^ 1;
            const float* Kn = Kg + (size_t)(kt + 1) * 64 * HD;
            const float* Vn = Vg + (size_t)(kt + 1) * 64 * HD;
            #pragma unroll
            for (int t = 0; t < 4; t++) {
                int l = tid + (t << 8);
                int j = l >> 4, dq = (l & 15) << 2;
                uint32_t off = (uint32_t)(nxt * KVB + j * KP + dq) * 4;
                cp_async16(ks_b + off, Kn + (size_t)j * HD + dq);
                cp_async16(vs_b + off, Vn + (size_t)j * HD + dq);
            }
            CP_COMMIT();
        }

        const float* Ksb = Ks + cur * KVB;
        const float* Vsb = Vs + cur * KVB;

        // S = Q K^T — packed pairs along d
        u64 s2[4][4];
        #pragma unroll
        for (int ii = 0; ii < 4; ii++)
            #pragma unroll
            for (int jj = 0; jj < 4; jj++) s2[ii][jj] = 0ull;

        for (int d0 = 0; d0 < 64; d0 += 4) {
            ulonglong2 q2[4];
            #pragma unroll
            for (int ii = 0; ii < 4; ii++)
                q2[ii] = *(const ulonglong2*)&Qs[(ty + 16 * ii) * 64 + d0];
            #pragma unroll
            for (int jj = 0; jj < 4; jj++) {
                ulonglong2 k2 = *(const ulonglong2*)&Ksb[(tx + 16 * jj) * KP + d0];
                #pragma unroll
                for (int ii = 0; ii < 4; ii++) {
                    ffma2(s2[ii][jj], q2[ii].x, k2.x);
                    ffma2(s2[ii][jj], q2[ii].y, k2.y);
                }
            }
        }

        float s[4][4];
        #pragma unroll
        for (int ii = 0; ii < 4; ii++)
            #pragma unroll
            for (int jj = 0; jj < 4; jj++) {
                float2 v = unpack2(s2[ii][jj]);
                s[ii][jj] = v.x + v.y;
            }

        // online softmax in exp2 domain
        #pragma unroll
        for (int ii = 0; ii < 4; ii++) {
            float mt = fmaxf(fmaxf(s[ii][0], s[ii][1]), fmaxf(s[ii][2], s[ii][3]));
            #pragma unroll
            for (int w = 8; w >= 1; w >>= 1)
                mt = fmaxf(mt, __shfl_xor_sync(0xffffffffu, mt, w));
            float mnew = fmaxf(m_i[ii], mt);
            float sum = 0.f;
            #pragma unroll
            for (int jj = 0; jj < 4; jj++) {
                float p = fast_exp2(s[ii][jj] - mnew);
                sum += p;
                Ps[(ty + 16 * ii) * 64 + tx + 16 * jj] = p;
            }
            #pragma unroll
            for (int w = 8; w >= 1; w >>= 1)
                sum += __shfl_xor_sync(0xffffffffu, sum, w);
            float sc = fast_exp2(m_i[ii] - mnew);
            l_i[ii] = l_i[ii] * sc + sum;
            m_i[ii] = mnew;
            u64 sc2 = pack2(sc, sc);
            mul2(o2[ii][0], sc2);
            mul2(o2[ii][1], sc2);
        }
        __syncwarp();   // Ps producer/consumer share a warp (same ty group)

        // O += P V  (packed pairs along d; P broadcast per (ii,dj))
        for (int j0 = 0; j0 < 64; j0 += 4) {
            float pa[4][4];
            #pragma unroll
            for (int ii = 0; ii < 4; ii++) {
                float4 pv = *(const float4*)&Ps[(ty + 16 * ii) * 64 + j0];
                pa[ii][0] = pv.x; pa[ii][1] = pv.y; pa[ii][2] = pv.z; pa[ii][3] = pv.w;
            }
            #pragma unroll
            for (int dj = 0; dj < 4; dj++) {
                ulonglong2 v2 = *(const ulonglong2*)&Vsb[(j0 + dj) * KP + 4 * tx];
                #pragma unroll
                for (int ii = 0; ii < 4; ii++) {
                    u64 pd = pack2(pa[ii][dj], pa[ii][dj]);
                    ffma2(o2[ii][0], pd, v2.x);
                    ffma2(o2[ii][1], pd, v2.y);
                }
            }
        }
    }

    // normalize and write to ctx [b,n,c]; thread owns dims 4tx..4tx+3
    const int b = bh / NH, h = bh % NH;
    #pragma unroll
    for (int ii = 0; ii < 4; ii++) {
        float inv = 1.f / l_i[ii];
        int n = qt * 64 + ty + 16 * ii;
        float* dst = g_ctx + ((size_t)(b * SEQ + n)) * CDIM + h * HD;
        float2 lo = unpack2(o2[ii][0]);
        float2 hi = unpack2(o2[ii][1]);
        float4 ov = { lo.x * inv, lo.y * inv, hi.x * inv, hi.y * inv };
        *(float4*)(dst + 4 * tx) = ov;
    }
}

// ---------------------------------------------------------------------------
// Launch
// ---------------------------------------------------------------------------
extern "C" void kernel_launch(void* const* d_in, const int* in_sizes, int n_in,
                              void* d_out, int out_size)
{
    (void)in_sizes; (void)n_in; (void)out_size;
    const float* x      = (const float*)d_in[0];   // [B,N,C]
    const float* w_qkv  = (const float*)d_in[1];   // [3C,C]
    const float* w_proj = (const float*)d_in[2];   // [C,C]
    const float* b_proj = (const float*)d_in[3];   // [C]
    float* out = (float*)d_out;                    // [B,N,C]

    // 1) QKV projection -> g_q (scaled), g_k, g_v
    dim3 g1((3 * CDIM) / 128, MTOT / 128);         // (18, 64)
    sgemm_kernel<0><<<g1, 256>>>(x, w_qkv, nullptr, nullptr);

    // 2) attention -> g_ctx
    cudaFuncSetAttribute(attn_kernel,
                         cudaFuncAttributeMaxDynamicSharedMemorySize,
                         ATTN_SMEM_BYTES);
    dim3 g2(SEQ / 64, BATCH * NH);                 // (16, 96)
    attn_kernel<<<g2, 256, ATTN_SMEM_BYTES>>>();

    // 3) output projection + bias -> out
    dim3 g3(CDIM / 128, MTOT / 128);               // (6, 64)
    sgemm_kernel<1><<<g3, 256>>>(x /*ignored*/, w_proj, b_proj, out);
}